// round 8
// baseline (speedup 1.0000x reference)
#include <cuda_runtime.h>
#include <cuda_bf16.h>
#include <cstdint>

#define N_NODES 100000
#define N_EDGES 625000
#define D_IN    128
#define D_HID   256

// ---------------------------------------------------------------------------
// Scratch (__device__ globals; allocation-free rule)
// ---------------------------------------------------------------------------
__device__ float g_agg[(size_t)N_NODES * D_IN];
__device__ float g_cnt[N_NODES];
// Fragment-major weight image: [img hi/lo][nt 16][c 4][ks 4][lane 32] uint4.
// Each uint4 = the 4 B-operand words (b0,b1,b2,b3) of an n16 x k16 tile:
//   .x: B[n0+l/4][k0+2(l%4)..+1]      .y: same, n+8
//   .z: same, k+8                      .w: n+8, k+8
// where n0 = nt*16, k0 = c*64 + ks*16, W_cat^T[n][k] (k<128: wl, else wr).
__device__ uint4 g_Wf[2 * 8192];

// ---------------------------------------------------------------------------
// Kernel 0: zero scratch
// ---------------------------------------------------------------------------
__global__ void zero_kernel() {
    int i = blockIdx.x * blockDim.x + threadIdx.x;
    int stride = gridDim.x * blockDim.x;
    const int total4 = N_NODES * D_IN / 4;
    float4 z = make_float4(0.f, 0.f, 0.f, 0.f);
    for (int j = i; j < total4; j += stride)
        ((float4*)g_agg)[j] = z;
    for (int j = i; j < N_NODES; j += stride)
        g_cnt[j] = 0.f;
}

// ---------------------------------------------------------------------------
// Kernel 1: edge scatter. One warp per edge, RED.128 vector reductions.
// ---------------------------------------------------------------------------
__global__ void edge_kernel(const float* __restrict__ x,
                            const int* __restrict__ ei) {
    int w = blockIdx.x * (blockDim.x >> 5) + (threadIdx.x >> 5);
    if (w >= N_EDGES) return;
    int lane = threadIdx.x & 31;

    int src = ei[w];
    int dst = ei[N_EDGES + w];

    float4 v = ((const float4*)(x + (long long)src * D_IN))[lane];
    float* p = g_agg + (long long)dst * D_IN + lane * 4;
    asm volatile("red.global.add.v4.f32 [%0], {%1,%2,%3,%4};"
                 :: "l"(p), "f"(v.x), "f"(v.y), "f"(v.z), "f"(v.w)
                 : "memory");
    if (lane == 0)
        atomicAdd(&g_cnt[dst], 1.0f);
}

// ---------------------------------------------------------------------------
// Kernel 2: build fragment-major bf16 hi/lo weight image
// ---------------------------------------------------------------------------
__device__ __forceinline__ float wcat(const float* wl, const float* wr,
                                      int n, int k) {
    return (k < 128) ? wl[k * 256 + n] : wr[(k - 128) * 256 + n];
}
__global__ void wconv_kernel(const float* __restrict__ wl,
                             const float* __restrict__ wr) {
    int idx = blockIdx.x * blockDim.x + threadIdx.x;   // 0..8191
    if (idx >= 8192) return;
    int lane = idx & 31;
    int ks   = (idx >> 5) & 3;
    int c    = (idx >> 7) & 3;
    int nt   = (idx >> 9) & 15;
    int n0 = nt * 16 + (lane >> 2);
    int k0 = c * 64 + ks * 16 + 2 * (lane & 3);

    uint32_t hiw[4], low[4];
#pragma unroll
    for (int j = 0; j < 4; j++) {
        int n = n0 + (j & 1) * 8;          // .x:n0 .y:n0+8 .z:n0 .w:n0+8
        int k = k0 + (j >> 1) * 8;         // .x,.y: k0   .z,.w: k0+8
        float v0 = wcat(wl, wr, n, k);
        float v1 = wcat(wl, wr, n, k + 1);
        __nv_bfloat16 h0 = __float2bfloat16_rn(v0);
        __nv_bfloat16 h1 = __float2bfloat16_rn(v1);
        __nv_bfloat16 l0 = __float2bfloat16_rn(v0 - __bfloat162float(h0));
        __nv_bfloat16 l1 = __float2bfloat16_rn(v1 - __bfloat162float(h1));
        hiw[j] = (uint32_t)__bfloat16_as_ushort(h0) |
                 ((uint32_t)__bfloat16_as_ushort(h1) << 16);
        low[j] = (uint32_t)__bfloat16_as_ushort(l0) |
                 ((uint32_t)__bfloat16_as_ushort(l1) << 16);
    }
    g_Wf[idx]        = make_uint4(hiw[0], hiw[1], hiw[2], hiw[3]);
    g_Wf[8192 + idx] = make_uint4(low[0], low[1], low[2], low[3]);
}

// ---------------------------------------------------------------------------
// PTX helpers (family-portable: sm_75/80+)
// ---------------------------------------------------------------------------
__device__ __forceinline__ uint32_t smem_u32(const void* p) {
    uint32_t a;
    asm("{ .reg .u64 t; cvta.to.shared.u64 t, %1; cvt.u32.u64 %0, t; }"
        : "=r"(a) : "l"(p));
    return a;
}
__device__ __forceinline__ void mma_bf16(float* d, const uint32_t* a,
                                         uint32_t b0, uint32_t b1) {
    asm volatile(
        "mma.sync.aligned.m16n8k16.row.col.f32.bf16.bf16.f32 "
        "{%0,%1,%2,%3}, {%4,%5,%6,%7}, {%8,%9}, {%0,%1,%2,%3};"
        : "+f"(d[0]), "+f"(d[1]), "+f"(d[2]), "+f"(d[3])
        : "r"(a[0]), "r"(a[1]), "r"(a[2]), "r"(a[3]), "r"(b0), "r"(b1));
}
#define LDSM4(d0, d1, d2, d3, addr) \
    asm volatile("ldmatrix.sync.aligned.m8n8.x4.shared.b16 {%0,%1,%2,%3}, [%4];" \
        : "=r"(d0), "=r"(d1), "=r"(d2), "=r"(d3) : "r"(addr))

// ---------------------------------------------------------------------------
// Kernel 3: bf16 hi/lo 3-pass mma.sync; B direct from L1-resident g_Wf.
// Block = 256 threads (8 warps), M=64 nodes, N=256, K=256 in 4 chunks of 64.
// A smem double-buffered (LDSM); B via LDG.128 fragments (no smem, no DMA).
// One __syncthreads per chunk. Register-resident epilogue (no s_h).
//
// SMEM/CTA (38,400 B):
//   A bufs [2 buf][2 img][64 rows][72 halfs] @ 0       (36,864)
//   s_bl [256] f32                           @ 36,864
//   s_inv [64] f32                           @ 37,888
//   epilogue overlays A region: s_part 16,384 @0; s_wh 17,408 @16,384;
//                               s_bh 64 @33,792
// ---------------------------------------------------------------------------
#define AST     144
#define A_IMG   9216
#define A_BUF   18432
#define OFF_BL  36864
#define OFF_INV 37888
#define SMEM_DYN 38400
#define E_WH  16384
#define E_BH  33792

__global__ __launch_bounds__(256, 2) void node_mma_kernel(
    const float* __restrict__ x,
    const float* __restrict__ wp, const float* __restrict__ bp,
    const float* __restrict__ ws, const float* __restrict__ bs,
    const float* __restrict__ bl,
    float* __restrict__ out)
{
    extern __shared__ float4 smem4[];
    char* smem = (char*)smem4;
    const uint32_t sb = smem_u32(smem);
    float* s_bl  = (float*)(smem + OFF_BL);
    float* s_inv = (float*)(smem + OFF_INV);

    const int t    = threadIdx.x;
    const int w    = t >> 5;
    const int lane = t & 31;
    const int lq   = lane >> 2;
    const int lr   = (lane & 3) * 2;
    const long long base = (long long)blockIdx.x * 64;

    if (t < 64) {
        long long node = base + t;
        if (node >= N_NODES) node = N_NODES - 1;
        s_inv[t] = 1.0f / fmaxf(g_cnt[node], 1.0f);
    }
    if (t < 256) s_bl[t] = bl[t];
    __syncthreads();

    const int m0    = (w & 1) * 32;    // 2 M-strips
    const int nbase = (w >> 1) * 64;   // 4 N-strips
    const int ntb   = (w >> 1) * 4;    // first n16-tile index

    float acc[64];
#pragma unroll
    for (int i = 0; i < 64; i++) acc[i] = 0.f;

    auto stageA = [&](int c, int buf) {   // 64 rows x 64 k = 1024 float4
        float4 v[4];
        int mm[4], kk[4];
#pragma unroll
        for (int it = 0; it < 4; it++) {
            int i = t + it * 256;
            int m = i >> 4, kl = (i & 15) * 4;
            mm[it] = m; kk[it] = kl;
            long long node = base + m;
            if (node >= N_NODES) node = N_NODES - 1;
            const float* src = (c < 2)
                ? (g_agg + node * D_IN + c * 64 + kl)
                : (x + node * D_IN + (c - 2) * 64 + kl);
            v[it] = *(const float4*)src;
        }
#pragma unroll
        for (int it = 0; it < 4; it++) {
            float4 vv = v[it];
            if (c < 2) {
                float inv = s_inv[mm[it]];
                vv.x *= inv; vv.y *= inv; vv.z *= inv; vv.w *= inv;
            }
            __nv_bfloat16 h0 = __float2bfloat16_rn(vv.x);
            __nv_bfloat16 h1 = __float2bfloat16_rn(vv.y);
            __nv_bfloat16 h2 = __float2bfloat16_rn(vv.z);
            __nv_bfloat16 h3 = __float2bfloat16_rn(vv.w);
            __nv_bfloat16 l0 = __float2bfloat16_rn(vv.x - __bfloat162float(h0));
            __nv_bfloat16 l1 = __float2bfloat16_rn(vv.y - __bfloat162float(h1));
            __nv_bfloat16 l2 = __float2bfloat16_rn(vv.z - __bfloat162float(h2));
            __nv_bfloat16 l3 = __float2bfloat16_rn(vv.w - __bfloat162float(h3));
            uint2 hp, lp;
            hp.x = (uint32_t)__bfloat16_as_ushort(h0) | ((uint32_t)__bfloat16_as_ushort(h1) << 16);
            hp.y = (uint32_t)__bfloat16_as_ushort(h2) | ((uint32_t)__bfloat16_as_ushort(h3) << 16);
            lp.x = (uint32_t)__bfloat16_as_ushort(l0) | ((uint32_t)__bfloat16_as_ushort(l1) << 16);
            lp.y = (uint32_t)__bfloat16_as_ushort(l2) | ((uint32_t)__bfloat16_as_ushort(l3) << 16);
            char* p = smem + buf * A_BUF + mm[it] * AST + kk[it] * 2;
            *(uint2*)p = hp;
            *(uint2*)(p + A_IMG) = lp;
        }
    };

    // ---- prologue ----
    stageA(0, 0);
    __syncthreads();

    const uint4* __restrict__ gW = g_Wf;
    const int tt    = lane >> 3;
    const int arow  = ((tt & 1) * 8) + (lane & 7);
    const int acol2 = ((tt >> 1) * 8) * 2;

    // ---- mainloop: one barrier per chunk; B straight from L1 ----
    for (int c = 0; c < 4; c++) {
        int cur = c & 1, nxt = cur ^ 1;
        if (c < 3) stageA(c + 1, nxt);

        const uint32_t Abase = sb + cur * A_BUF;
#pragma unroll
        for (int pass = 0; pass < 3; pass++) {
            uint32_t Ab = Abase + ((pass == 2) ? A_IMG : 0);
            const int bimg = (pass == 1) ? 8192 : 0;
#pragma unroll
            for (int ks = 0; ks < 4; ks++) {
                int kb = ks * 32;
                uint32_t a0[4], a1[4];
                uint32_t ad = Ab + (m0 + arow) * AST + kb + acol2;
                LDSM4(a0[0], a0[1], a0[2], a0[3], ad);
                LDSM4(a1[0], a1[1], a1[2], a1[3], ad + 16 * AST);
                uint4 bb[4];
#pragma unroll
                for (int j = 0; j < 4; j++)
                    bb[j] = gW[bimg + ((ntb + j) << 9) + (c << 7) + (ks << 5) + lane];
#pragma unroll
                for (int j = 0; j < 4; j++) {
                    int nt0 = j * 2, nt1 = j * 2 + 1;
                    mma_bf16(acc + nt0 * 4,      a0, bb[j].x, bb[j].z);
                    mma_bf16(acc + nt1 * 4,      a0, bb[j].y, bb[j].w);
                    mma_bf16(acc + 32 + nt0 * 4, a1, bb[j].x, bb[j].z);
                    mma_bf16(acc + 32 + nt1 * 4, a1, bb[j].y, bb[j].w);
                }
            }
        }
        __syncthreads();
    }

    // ---- epilogue: overlay A region ----
    float* s_part = (float*)smem;              // [4 nstrip][64 m][16]
    float* s_wh   = (float*)(smem + E_WH);     // [256][17]
    float* s_bh   = (float*)(smem + E_BH);

    for (int i = t; i < 13 * 256; i += 256) {
        int j = i & 255, cc = i >> 8;
        s_wh[j * 17 + cc] = (cc < 7) ? wp[j * 7 + cc] : ws[j * 6 + (cc - 7)];
    }
    if (t < 16) s_bh[t] = (t < 7) ? bp[t] : (t < 13 ? bs[t - 7] : 0.f);
    __syncthreads();

    // per-warp head partials from registers, butterfly over lr lanes
    const int nstrip = w >> 1;
#pragma unroll
    for (int mi = 0; mi < 2; mi++) {
        float pr0[13], pr1[13];
#pragma unroll
        for (int cc = 0; cc < 13; cc++) { pr0[cc] = 0.f; pr1[cc] = 0.f; }
#pragma unroll
        for (int nt = 0; nt < 8; nt++) {
            int col0 = nbase + nt * 8 + lr;
            float b0 = s_bl[col0], b1 = s_bl[col0 + 1];
            const float* d = acc + mi * 32 + nt * 4;
            float h00 = fmaxf(d[0] + b0, 0.f), h01 = fmaxf(d[1] + b1, 0.f);
            float h10 = fmaxf(d[2] + b0, 0.f), h11 = fmaxf(d[3] + b1, 0.f);
            const float* w0 = s_wh + col0 * 17;
            const float* w1 = w0 + 17;
#pragma unroll
            for (int cc = 0; cc < 13; cc++) {
                float wa = w0[cc], wb = w1[cc];
                pr0[cc] = fmaf(h00, wa, fmaf(h01, wb, pr0[cc]));
                pr1[cc] = fmaf(h10, wa, fmaf(h11, wb, pr1[cc]));
            }
        }
#pragma unroll
        for (int cc = 0; cc < 13; cc++) {
            pr0[cc] += __shfl_xor_sync(0xffffffff, pr0[cc], 1);
            pr0[cc] += __shfl_xor_sync(0xffffffff, pr0[cc], 2);
            pr1[cc] += __shfl_xor_sync(0xffffffff, pr1[cc], 1);
            pr1[cc] += __shfl_xor_sync(0xffffffff, pr1[cc], 2);
        }
        if ((lane & 3) == 0) {
            int r = m0 + mi * 16 + lq;
#pragma unroll
            for (int cc = 0; cc < 13; cc++) {
                s_part[nstrip * 1024 + r * 16 + cc]       = pr0[cc];
                s_part[nstrip * 1024 + (r + 8) * 16 + cc] = pr1[cc];
            }
        }
    }
    __syncthreads();

    // final reduce + log_softmax + writeout
    if (t < 64) {
        long long node = base + t;
        if (node < N_NODES) {
            float o[13];
#pragma unroll
            for (int cc = 0; cc < 13; cc++) {
                o[cc] = s_bh[cc] + s_part[t * 16 + cc] + s_part[1024 + t * 16 + cc]
                      + s_part[2048 + t * 16 + cc] + s_part[3072 + t * 16 + cc];
            }
            float mx = o[0];
#pragma unroll
            for (int cc = 1; cc < 7; cc++) mx = fmaxf(mx, o[cc]);
            float s = 0.f;
#pragma unroll
            for (int cc = 0; cc < 7; cc++) s += __expf(o[cc] - mx);
            float lse = mx + __logf(s);
#pragma unroll
            for (int cc = 0; cc < 7; cc++) out[node * 7 + cc] = o[cc] - lse;

            mx = o[7];
#pragma unroll
            for (int cc = 8; cc < 13; cc++) mx = fmaxf(mx, o[cc]);
            s = 0.f;
#pragma unroll
            for (int cc = 7; cc < 13; cc++) s += __expf(o[cc] - mx);
            lse = mx + __logf(s);
            float* out2 = out + (long long)N_NODES * 7;
#pragma unroll
            for (int cc = 0; cc < 6; cc++) out2[node * 6 + cc] = o[7 + cc] - lse;
        }
    }
}

// ---------------------------------------------------------------------------
extern "C" void kernel_launch(void* const* d_in, const int* in_sizes, int n_in,
                              void* d_out, int out_size) {
    const float* x  = (const float*)d_in[0];
    const int*   ei = (const int*)d_in[1];
    const float* wl = (const float*)d_in[2];
    const float* bl = (const float*)d_in[3];
    const float* wr = (const float*)d_in[4];
    const float* wp = (const float*)d_in[5];
    const float* bp = (const float*)d_in[6];
    const float* ws = (const float*)d_in[7];
    const float* bs = (const float*)d_in[8];
    float* out = (float*)d_out;

    cudaFuncSetAttribute(node_mma_kernel,
                         cudaFuncAttributeMaxDynamicSharedMemorySize, SMEM_DYN);

    zero_kernel<<<512, 256>>>();
    wconv_kernel<<<32, 256>>>(wl, wr);

    int edge_blocks = (N_EDGES + 7) / 8;   // one warp per edge
    edge_kernel<<<edge_blocks, 256>>>(x, ei);

    int node_blocks = (N_NODES + 63) / 64;   // 1563
    node_mma_kernel<<<node_blocks, 256, SMEM_DYN>>>(x, wp, bp, ws, bs, bl, out);
}

// round 9
// speedup vs baseline: 1.1256x; 1.1256x over previous
#include <cuda_runtime.h>
#include <cuda_bf16.h>
#include <cstdint>

#define N_NODES 100000
#define N_EDGES 625000
#define D_IN    128
#define D_HID   256

// ---------------------------------------------------------------------------
// Scratch (__device__ globals; allocation-free rule)
// ---------------------------------------------------------------------------
__device__ float g_agg[(size_t)N_NODES * D_IN];
__device__ float g_cnt[N_NODES];
// Weight image W_cat^T: [img: hi/lo][n (256)][k (256)] bf16 (512B rows).
__device__ __nv_bfloat16 g_Wt[2][256 * 256];

// ---------------------------------------------------------------------------
// Kernel 0: zero scratch
// ---------------------------------------------------------------------------
__global__ void zero_kernel() {
    int i = blockIdx.x * blockDim.x + threadIdx.x;
    int stride = gridDim.x * blockDim.x;
    const int total4 = N_NODES * D_IN / 4;
    float4 z = make_float4(0.f, 0.f, 0.f, 0.f);
    for (int j = i; j < total4; j += stride)
        ((float4*)g_agg)[j] = z;
    for (int j = i; j < N_NODES; j += stride)
        g_cnt[j] = 0.f;
}

// ---------------------------------------------------------------------------
// Kernel 1: edge scatter. One warp per edge, RED.128 vector reductions.
// ---------------------------------------------------------------------------
__global__ void edge_kernel(const float* __restrict__ x,
                            const int* __restrict__ ei) {
    int w = blockIdx.x * (blockDim.x >> 5) + (threadIdx.x >> 5);
    if (w >= N_EDGES) return;
    int lane = threadIdx.x & 31;

    int src = ei[w];
    int dst = ei[N_EDGES + w];

    float4 v = ((const float4*)(x + (long long)src * D_IN))[lane];
    float* p = g_agg + (long long)dst * D_IN + lane * 4;
    asm volatile("red.global.add.v4.f32 [%0], {%1,%2,%3,%4};"
                 :: "l"(p), "f"(v.x), "f"(v.y), "f"(v.z), "f"(v.w)
                 : "memory");
    if (lane == 0)
        atomicAdd(&g_cnt[dst], 1.0f);
}

// ---------------------------------------------------------------------------
// Kernel 2: build bf16 hi/lo weight image (W_cat^T, [n][k] layout)
// ---------------------------------------------------------------------------
__global__ void wconv_kernel(const float* __restrict__ wl,
                             const float* __restrict__ wr) {
    int idx = blockIdx.x * blockDim.x + threadIdx.x;
    if (idx >= 256 * 256) return;
    int n = idx >> 8;
    int k = idx & 255;
    float v = (k < 128) ? wl[k * 256 + n] : wr[(k - 128) * 256 + n];
    __nv_bfloat16 hi = __float2bfloat16_rn(v);
    __nv_bfloat16 lo = __float2bfloat16_rn(v - __bfloat162float(hi));
    g_Wt[0][idx] = hi;
    g_Wt[1][idx] = lo;
}

// ---------------------------------------------------------------------------
// PTX helpers (family-portable: sm_75/80+)
// ---------------------------------------------------------------------------
__device__ __forceinline__ uint32_t smem_u32(const void* p) {
    uint32_t a;
    asm("{ .reg .u64 t; cvta.to.shared.u64 t, %1; cvt.u32.u64 %0, t; }"
        : "=r"(a) : "l"(p));
    return a;
}
__device__ __forceinline__ void mma_bf16(float* d, const uint32_t* a,
                                         uint32_t b0, uint32_t b1) {
    asm volatile(
        "mma.sync.aligned.m16n8k16.row.col.f32.bf16.bf16.f32 "
        "{%0,%1,%2,%3}, {%4,%5,%6,%7}, {%8,%9}, {%0,%1,%2,%3};"
        : "+f"(d[0]), "+f"(d[1]), "+f"(d[2]), "+f"(d[3])
        : "r"(a[0]), "r"(a[1]), "r"(a[2]), "r"(a[3]), "r"(b0), "r"(b1));
}
#define LDSM4(d0, d1, d2, d3, addr) \
    asm volatile("ldmatrix.sync.aligned.m8n8.x4.shared.b16 {%0,%1,%2,%3}, [%4];" \
        : "=r"(d0), "=r"(d1), "=r"(d2), "=r"(d3) : "r"(addr))
#define CPASYNC16(dst, src) \
    asm volatile("cp.async.ca.shared.global [%0], [%1], 16;" :: "r"(dst), "l"(src))
#define CPCOMMIT() asm volatile("cp.async.commit_group;" ::: "memory")
#define CPWAIT0()  asm volatile("cp.async.wait_group 0;" ::: "memory")

// ---------------------------------------------------------------------------
// Kernel 3: bf16 hi/lo 3-pass mma.sync node kernel, 2 CTAs/SM, fully
// double-buffered (A and B) with k=32 chunks so all DMA hides under MMA.
// Block = 256 threads (8 warps), M=64 nodes, N=256, K=256 in 8 chunks of 32.
// Register-resident epilogue (shfl-reduced heads, no s_h).
//
// SMEM/CTA (103,680 B -> 2 CTAs/SM):
//   A bufs [2 buf][2 img][64 rows][40 halfs] @ 0        (20,480)
//   B bufs [2 buf][2 img][256 rows][40 halfs] @ 20,480  (81,920)
//   s_bl [256] f32                            @ 102,400
//   s_inv [64] f32                            @ 103,424
//   epilogue overlays A/B: s_part 16K @0; s_wh @16,384; s_bh @33,792
// ---------------------------------------------------------------------------
#define AST     80            // bytes per smem row (32 halfs + 16B pad)
#define A_IMG   5120          // 64*80
#define A_BUF   10240         // 2 imgs
#define B_OFF   20480
#define B_IMG   20480         // 256*80
#define B_BUF   40960         // 2 imgs
#define OFF_BL  102400
#define OFF_INV 103424
#define SMEM_DYN 103680
#define E_WH  16384
#define E_BH  33792

__global__ __launch_bounds__(256, 2) void node_mma_kernel(
    const float* __restrict__ x,
    const float* __restrict__ wp, const float* __restrict__ bp,
    const float* __restrict__ ws, const float* __restrict__ bs,
    const float* __restrict__ bl,
    float* __restrict__ out)
{
    extern __shared__ float4 smem4[];
    char* smem = (char*)smem4;
    const uint32_t sb = smem_u32(smem);
    float* s_bl  = (float*)(smem + OFF_BL);
    float* s_inv = (float*)(smem + OFF_INV);

    const int t    = threadIdx.x;
    const int w    = t >> 5;
    const int lane = t & 31;
    const int lq   = lane >> 2;
    const int lr   = (lane & 3) * 2;
    const long long base = (long long)blockIdx.x * 64;

    if (t < 64) {
        long long node = base + t;
        if (node >= N_NODES) node = N_NODES - 1;
        s_inv[t] = 1.0f / fmaxf(g_cnt[node], 1.0f);
    }
    if (t < 256) s_bl[t] = bl[t];
    __syncthreads();

    const int m0    = (w & 1) * 32;    // 2 M-strips
    const int nbase = (w >> 1) * 64;   // 4 N-strips

    float acc[64];
#pragma unroll
    for (int i = 0; i < 64; i++) acc[i] = 0.f;

    // ---- staging helpers (k=32 chunks) ----
    auto stageB = [&](int c, int buf) {   // 2 img x 256 rows x 64B via cp.async
#pragma unroll
        for (int img = 0; img < 2; img++) {
            const char* gs = (const char*)&g_Wt[img][0];
#pragma unroll
            for (int it = 0; it < 4; it++) {
                int i = t + it * 256;     // 0..1023
                int n = i >> 2, q = i & 3;
                uint32_t dst = sb + B_OFF + buf * B_BUF + img * B_IMG + n * AST + q * 16;
                CPASYNC16(dst, gs + n * 512 + c * 64 + q * 16);
            }
        }
    };
    auto stageA = [&](int c, int buf) {   // 64 rows x 32 k = 512 float4
#pragma unroll
        for (int it = 0; it < 2; it++) {
            int i = t + it * 256;         // 0..511
            int m = i >> 3, kl = (i & 7) * 4;
            long long node = base + m;
            if (node >= N_NODES) node = N_NODES - 1;
            const float* src = (c < 4)
                ? (g_agg + node * D_IN + c * 32 + kl)
                : (x + node * D_IN + (c - 4) * 32 + kl);
            float4 vv = *(const float4*)src;
            if (c < 4) {
                float inv = s_inv[m];
                vv.x *= inv; vv.y *= inv; vv.z *= inv; vv.w *= inv;
            }
            __nv_bfloat16 h0 = __float2bfloat16_rn(vv.x);
            __nv_bfloat16 h1 = __float2bfloat16_rn(vv.y);
            __nv_bfloat16 h2 = __float2bfloat16_rn(vv.z);
            __nv_bfloat16 h3 = __float2bfloat16_rn(vv.w);
            __nv_bfloat16 l0 = __float2bfloat16_rn(vv.x - __bfloat162float(h0));
            __nv_bfloat16 l1 = __float2bfloat16_rn(vv.y - __bfloat162float(h1));
            __nv_bfloat16 l2 = __float2bfloat16_rn(vv.z - __bfloat162float(h2));
            __nv_bfloat16 l3 = __float2bfloat16_rn(vv.w - __bfloat162float(h3));
            uint2 hp, lp;
            hp.x = (uint32_t)__bfloat16_as_ushort(h0) | ((uint32_t)__bfloat16_as_ushort(h1) << 16);
            hp.y = (uint32_t)__bfloat16_as_ushort(h2) | ((uint32_t)__bfloat16_as_ushort(h3) << 16);
            lp.x = (uint32_t)__bfloat16_as_ushort(l0) | ((uint32_t)__bfloat16_as_ushort(l1) << 16);
            lp.y = (uint32_t)__bfloat16_as_ushort(l2) | ((uint32_t)__bfloat16_as_ushort(l3) << 16);
            char* p = smem + buf * A_BUF + m * AST + kl * 2;
            *(uint2*)p = hp;
            *(uint2*)(p + A_IMG) = lp;
        }
    };

    // ---- prologue: chunk 0 into buffer 0 ----
    stageB(0, 0); CPCOMMIT();
    stageA(0, 0);
    CPWAIT0();
    __syncthreads();

    const int tt    = lane >> 3;
    const int arow  = ((tt & 1) * 8) + (lane & 7);
    const int acol2 = ((tt >> 1) * 8) * 2;

    // ---- mainloop: 8 chunks, DMA for c+1 overlaps MMAs of c ----
    for (int c = 0; c < 8; c++) {
        int cur = c & 1, nxt = cur ^ 1;
        if (c < 7) {
            stageB(c + 1, nxt); CPCOMMIT();
            stageA(c + 1, nxt);
        }

        const uint32_t Abase = sb + cur * A_BUF;
        const uint32_t Bbase = sb + B_OFF + cur * B_BUF;
#pragma unroll
        for (int pass = 0; pass < 3; pass++) {
            uint32_t Ab = Abase + ((pass == 2) ? A_IMG : 0);
            uint32_t Bb = Bbase + ((pass == 1) ? B_IMG : 0);
#pragma unroll
            for (int ks = 0; ks < 2; ks++) {
                int kb = ks * 32;         // 16 halfs = 32B per k-step
                uint32_t a0[4], a1[4], b[4][4];
                uint32_t ad = Ab + (m0 + arow) * AST + kb + acol2;
                LDSM4(a0[0], a0[1], a0[2], a0[3], ad);
                LDSM4(a1[0], a1[1], a1[2], a1[3], ad + 16 * AST);
#pragma unroll
                for (int j = 0; j < 4; j++) {
                    uint32_t bd = Bb + (nbase + j * 16 + arow) * AST + kb + acol2;
                    LDSM4(b[j][0], b[j][1], b[j][2], b[j][3], bd);
                }
#pragma unroll
                for (int j = 0; j < 4; j++) {
                    int nt0 = j * 2, nt1 = j * 2 + 1;
                    mma_bf16(acc + nt0 * 4,      a0, b[j][0], b[j][2]);
                    mma_bf16(acc + nt1 * 4,      a0, b[j][1], b[j][3]);
                    mma_bf16(acc + 32 + nt0 * 4, a1, b[j][0], b[j][2]);
                    mma_bf16(acc + 32 + nt1 * 4, a1, b[j][1], b[j][3]);
                }
            }
        }
        if (c < 7) CPWAIT0();
        __syncthreads();
    }

    // ---- epilogue: overlay A/B region (register-resident heads) ----
    float* s_part = (float*)smem;              // [4 nstrip][64 m][16]
    float* s_wh   = (float*)(smem + E_WH);     // [256][17]
    float* s_bh   = (float*)(smem + E_BH);

    for (int i = t; i < 13 * 256; i += 256) {
        int j = i & 255, cc = i >> 8;
        s_wh[j * 17 + cc] = (cc < 7) ? wp[j * 7 + cc] : ws[j * 6 + (cc - 7)];
    }
    if (t < 16) s_bh[t] = (t < 7) ? bp[t] : (t < 13 ? bs[t - 7] : 0.f);
    __syncthreads();

    const int nstrip = w >> 1;
#pragma unroll
    for (int mi = 0; mi < 2; mi++) {
        float pr0[13], pr1[13];
#pragma unroll
        for (int cc = 0; cc < 13; cc++) { pr0[cc] = 0.f; pr1[cc] = 0.f; }
#pragma unroll
        for (int nt = 0; nt < 8; nt++) {
            int col0 = nbase + nt * 8 + lr;
            float b0 = s_bl[col0], b1 = s_bl[col0 + 1];
            const float* d = acc + mi * 32 + nt * 4;
            float h00 = fmaxf(d[0] + b0, 0.f), h01 = fmaxf(d[1] + b1, 0.f);
            float h10 = fmaxf(d[2] + b0, 0.f), h11 = fmaxf(d[3] + b1, 0.f);
            const float* w0 = s_wh + col0 * 17;
            const float* w1 = w0 + 17;
#pragma unroll
            for (int cc = 0; cc < 13; cc++) {
                float wa = w0[cc], wb = w1[cc];
                pr0[cc] = fmaf(h00, wa, fmaf(h01, wb, pr0[cc]));
                pr1[cc] = fmaf(h10, wa, fmaf(h11, wb, pr1[cc]));
            }
        }
#pragma unroll
        for (int cc = 0; cc < 13; cc++) {
            pr0[cc] += __shfl_xor_sync(0xffffffff, pr0[cc], 1);
            pr0[cc] += __shfl_xor_sync(0xffffffff, pr0[cc], 2);
            pr1[cc] += __shfl_xor_sync(0xffffffff, pr1[cc], 1);
            pr1[cc] += __shfl_xor_sync(0xffffffff, pr1[cc], 2);
        }
        if ((lane & 3) == 0) {
            int r = m0 + mi * 16 + lq;
#pragma unroll
            for (int cc = 0; cc < 13; cc++) {
                s_part[nstrip * 1024 + r * 16 + cc]       = pr0[cc];
                s_part[nstrip * 1024 + (r + 8) * 16 + cc] = pr1[cc];
            }
        }
    }
    __syncthreads();

    // final reduce + log_softmax + writeout
    if (t < 64) {
        long long node = base + t;
        if (node < N_NODES) {
            float o[13];
#pragma unroll
            for (int cc = 0; cc < 13; cc++) {
                o[cc] = s_bh[cc] + s_part[t * 16 + cc] + s_part[1024 + t * 16 + cc]
                      + s_part[2048 + t * 16 + cc] + s_part[3072 + t * 16 + cc];
            }
            float mx = o[0];
#pragma unroll
            for (int cc = 1; cc < 7; cc++) mx = fmaxf(mx, o[cc]);
            float s = 0.f;
#pragma unroll
            for (int cc = 0; cc < 7; cc++) s += __expf(o[cc] - mx);
            float lse = mx + __logf(s);
#pragma unroll
            for (int cc = 0; cc < 7; cc++) out[node * 7 + cc] = o[cc] - lse;

            mx = o[7];
#pragma unroll
            for (int cc = 8; cc < 13; cc++) mx = fmaxf(mx, o[cc]);
            s = 0.f;
#pragma unroll
            for (int cc = 7; cc < 13; cc++) s += __expf(o[cc] - mx);
            lse = mx + __logf(s);
            float* out2 = out + (long long)N_NODES * 7;
#pragma unroll
            for (int cc = 0; cc < 6; cc++) out2[node * 6 + cc] = o[7 + cc] - lse;
        }
    }
}

// ---------------------------------------------------------------------------
extern "C" void kernel_launch(void* const* d_in, const int* in_sizes, int n_in,
                              void* d_out, int out_size) {
    const float* x  = (const float*)d_in[0];
    const int*   ei = (const int*)d_in[1];
    const float* wl = (const float*)d_in[2];
    const float* bl = (const float*)d_in[3];
    const float* wr = (const float*)d_in[4];
    const float* wp = (const float*)d_in[5];
    const float* bp = (const float*)d_in[6];
    const float* ws = (const float*)d_in[7];
    const float* bs = (const float*)d_in[8];
    float* out = (float*)d_out;

    cudaFuncSetAttribute(node_mma_kernel,
                         cudaFuncAttributeMaxDynamicSharedMemorySize, SMEM_DYN);

    zero_kernel<<<512, 256>>>();
    wconv_kernel<<<256, 256>>>(wl, wr);

    int edge_blocks = (N_EDGES + 7) / 8;   // one warp per edge
    edge_kernel<<<edge_blocks, 256>>>(x, ei);

    int node_blocks = (N_NODES + 63) / 64;   // 1563
    node_mma_kernel<<<node_blocks, 256, SMEM_DYN>>>(x, wp, bp, ws, bs, bl, out);
}